// round 9
// baseline (speedup 1.0000x reference)
#include <cuda_runtime.h>
#include <cuda_bf16.h>
#include <cstdint>

#define BB 8
#define SS 2048
#define EE 512
#define MTOT (BB * SS)

// ---------------------------------------------------------------------------
// Scratch (__device__ globals; no allocation anywhere)
// ---------------------------------------------------------------------------
__device__ __nv_bfloat16 g_Qhi[(size_t)MTOT * EE], g_Qlo[(size_t)MTOT * EE];
__device__ __nv_bfloat16 g_Khi[(size_t)MTOT * EE];
__device__ __nv_bfloat16 g_Wqhi[EE * EE], g_Wqlo[EE * EE];
__device__ __nv_bfloat16 g_Wkhi[EE * EE];
__device__ __nv_bfloat16 g_Wvhi[EE * EE];
__device__ __nv_bfloat16 g_Wphi[EE * EE];
__device__ float         g_qf [(size_t)MTOT * EE];
__device__ __nv_bfloat16 g_qhi[(size_t)MTOT * EE];
__device__ __nv_bfloat16 g_khi[(size_t)MTOT * EE];
__device__ __nv_bfloat16 g_vThi[(size_t)BB * EE * SS];
__device__ __nv_bfloat16 g_phi[(size_t)BB * SS * SS];   // scores (bf16) -> probs in place
__device__ __nv_bfloat16 g_aohi[(size_t)MTOT * EE];
__device__ int           g_mask4;

// ---------------------------------------------------------------------------
// Helpers (baseline PTX only; legal at .target sm_103)
// ---------------------------------------------------------------------------
__device__ __forceinline__ uint32_t smem_u32(const void* p) {
    uint32_t a;
    asm("{ .reg .u64 t; cvta.to.shared.u64 t, %1; cvt.u32.u64 %0, t; }"
        : "=r"(a) : "l"(p));
    return a;
}
__device__ __forceinline__ void cpasync16(uint32_t dst, const void* src) {
    asm volatile("cp.async.cg.shared.global [%0], [%1], 16;"
                 :: "r"(dst), "l"(src) : "memory");
}
#define CP_COMMIT() asm volatile("cp.async.commit_group;" ::: "memory")
#define CP_WAIT2()  asm volatile("cp.async.wait_group 2;" ::: "memory")
#define CP_WAIT1()  asm volatile("cp.async.wait_group 1;" ::: "memory")
#define CP_WAIT0()  asm volatile("cp.async.wait_group 0;" ::: "memory")

__device__ __forceinline__ void ldsm4(uint32_t* r, uint32_t addr) {
    asm volatile("ldmatrix.sync.aligned.m8n8.x4.shared.b16 {%0,%1,%2,%3}, [%4];"
                 : "=r"(r[0]), "=r"(r[1]), "=r"(r[2]), "=r"(r[3]) : "r"(addr));
}
__device__ __forceinline__ void mma_bf16(float* d, const uint32_t* a, const uint32_t* b) {
    asm volatile(
        "mma.sync.aligned.m16n8k16.row.col.f32.bf16.bf16.f32 "
        "{%0,%1,%2,%3}, {%4,%5,%6,%7}, {%8,%9}, {%0,%1,%2,%3};"
        : "+f"(d[0]), "+f"(d[1]), "+f"(d[2]), "+f"(d[3])
        : "r"(a[0]), "r"(a[1]), "r"(a[2]), "r"(a[3]), "r"(b[0]), "r"(b[1]));
}

// SMEM rows: 64 bf16 (128 B data), pitch 144 B => conflict-free ldmatrix
#define PITCH    144
#define BTILE_B  (128 * PITCH)          // B tile is always 128 rows

// ---------------------------------------------------------------------------
// HMMA NT GEMM: C[M,N] = alpha * A[M,K] * B[N,K]^T, bf16, fp32 acc.
// NPROD=1: Ah*Bh.  NPROD=3: Ah*Bh + Ah*Bl + Al*Bh.
// Block BMx128, BK=64, 256 threads (8 warps: 4 m x 2 n), OCC CTAs/SM.
// STG-stage cp.async pipeline, one __syncthreads per K-iter, fragment
// double-buffering across ks steps. Requires M%BM==0, N%128==0, K%64==0.
// ---------------------------------------------------------------------------
template <int BM, int STG, int NPROD, int OCC,
          bool BIAS, bool RESID, bool WF32, bool WHI>
__global__ void __launch_bounds__(256, OCC)
hmma_gemm(const __nv_bfloat16* __restrict__ Ahi, const __nv_bfloat16* __restrict__ Alo,
          const __nv_bfloat16* __restrict__ Bhi, const __nv_bfloat16* __restrict__ Blo,
          float* __restrict__ C, __nv_bfloat16* __restrict__ Chi,
          int M, int N, int K,
          long long sA, long long sB, long long sC,
          float alpha, const float* __restrict__ bias, const float* __restrict__ resid) {
    constexpr int MT      = BM / 64;             // m16 tiles per warp
    constexpr uint32_t ATILE = (uint32_t)BM * PITCH;
    constexpr uint32_t OFF_AL = ATILE;                                // NPROD==3
    constexpr uint32_t OFF_BH = (NPROD == 3) ? 2u * ATILE : ATILE;
    constexpr uint32_t OFF_BL = OFF_BH + BTILE_B;                     // NPROD==3
    constexpr uint32_t STAGE_B =
        ((NPROD == 3) ? 2u : 1u) * ATILE + ((NPROD == 3) ? 2u : 1u) * BTILE_B;

    extern __shared__ __align__(128) char smem[];
    const uint32_t sb = smem_u32(smem);

    const int tid  = threadIdx.x;
    const int wid  = tid >> 5;
    const int lane = tid & 31;
    const int bz   = blockIdx.z;
    const int m0   = blockIdx.y * BM;
    const int n0   = blockIdx.x * 128;

    const __nv_bfloat16* Ah = Ahi + (long long)bz * sA;
    const __nv_bfloat16* Al = (NPROD == 3) ? (Alo + (long long)bz * sA) : nullptr;
    const __nv_bfloat16* Bh = Bhi + (long long)bz * sB;
    const __nv_bfloat16* Bl = (NPROD == 3) ? (Blo + (long long)bz * sB) : nullptr;

    const int nkt = K >> 6;

    auto FETCH = [&](int kt, int st) {
        const uint32_t base = sb + (uint32_t)st * STAGE_B;
#pragma unroll
        for (int t = 0; t < BM / 32; t++) {
            const int c   = tid + t * 256;
            const int row = c >> 3;
            const int cp  = c & 7;
            const uint32_t doff = row * PITCH + cp * 16;
            const long long ga = (long long)(m0 + row) * K + (kt << 6) + cp * 8;
            cpasync16(base + doff, Ah + ga);
            if (NPROD == 3) cpasync16(base + OFF_AL + doff, Al + ga);
        }
#pragma unroll
        for (int t = 0; t < 4; t++) {
            const int c   = tid + t * 256;
            const int row = c >> 3;
            const int cp  = c & 7;
            const uint32_t doff = row * PITCH + cp * 16;
            const long long gb = (long long)(n0 + row) * K + (kt << 6) + cp * 8;
            cpasync16(base + OFF_BH + doff, Bh + gb);
            if (NPROD == 3) cpasync16(base + OFF_BL + doff, Bl + gb);
        }
        CP_COMMIT();
    };

    float acc[MT][8][4];
#pragma unroll
    for (int mt = 0; mt < MT; mt++)
#pragma unroll
        for (int nt = 0; nt < 8; nt++)
#pragma unroll
            for (int j = 0; j < 4; j++) acc[mt][nt][j] = 0.f;

    const int wm = (wid & 3) * (BM / 4);   // warp m offset
    const int wn = (wid >> 2) * 64;        // warp n offset
    const int i8 = lane & 7;
    const uint32_t a_off = (uint32_t)(i8 + ((lane >> 3) & 1) * 8) * PITCH + (lane >> 4) * 16;
    const uint32_t b_off = (uint32_t)(i8 + ((lane >> 4) & 1) * 8) * PITCH + ((lane >> 3) & 1) * 16;

    auto COMPUTE = [&](int st) {
        const uint32_t base = sb + (uint32_t)st * STAGE_B;
        const uint32_t aAh = base + (uint32_t)wm * PITCH + a_off;
        const uint32_t aBh = base + OFF_BH + (uint32_t)wn * PITCH + b_off;
        const uint32_t aBl = base + OFF_BL + (uint32_t)wn * PITCH + b_off;

        uint32_t ah[2][MT][4], al[2][MT][4], bh[2][4][4], bl[2][4][4];

        auto LOADF = [&](int ks, int buf) {
#pragma unroll
            for (int mt = 0; mt < MT; mt++) {
                ldsm4(ah[buf][mt], aAh + mt * 16 * PITCH + ks * 32);
                if (NPROD == 3) ldsm4(al[buf][mt], aAh + OFF_AL + mt * 16 * PITCH + ks * 32);
            }
#pragma unroll
            for (int nt = 0; nt < 4; nt++) {
                ldsm4(bh[buf][nt], aBh + nt * 16 * PITCH + ks * 32);
                if (NPROD == 3) ldsm4(bl[buf][nt], aBl + nt * 16 * PITCH + ks * 32);
            }
        };

        LOADF(0, 0);
#pragma unroll
        for (int ks = 0; ks < 4; ks++) {
            const int cur = ks & 1;
            if (ks < 3) LOADF(ks + 1, cur ^ 1);
#pragma unroll
            for (int mt = 0; mt < MT; mt++)
#pragma unroll
                for (int nt = 0; nt < 8; nt++)
                    mma_bf16(acc[mt][nt], ah[cur][mt], &bh[cur][nt >> 1][(nt & 1) * 2]);
            if (NPROD == 3) {
#pragma unroll
                for (int mt = 0; mt < MT; mt++)
#pragma unroll
                    for (int nt = 0; nt < 8; nt++)
                        mma_bf16(acc[mt][nt], ah[cur][mt], &bl[cur][nt >> 1][(nt & 1) * 2]);
#pragma unroll
                for (int mt = 0; mt < MT; mt++)
#pragma unroll
                    for (int nt = 0; nt < 8; nt++)
                        mma_bf16(acc[mt][nt], al[cur][mt], &bh[cur][nt >> 1][(nt & 1) * 2]);
            }
        }
    };

    FETCH(0, 0);
    FETCH(1, 1);
    if (STG == 4) FETCH(2, 2);

    for (int kt = 0; kt < nkt; kt++) {
        const int st  = kt % STG;
        const int rem = nkt - kt - 1;
        if (STG == 4) {
            if (rem >= 2) { CP_WAIT2(); }
            else if (rem == 1) { CP_WAIT1(); }
            else { CP_WAIT0(); }
        } else {
            if (rem >= 1) { CP_WAIT1(); }
            else { CP_WAIT0(); }
        }
        __syncthreads();
        if (kt + STG - 1 < nkt) FETCH(kt + STG - 1, (kt + STG - 1) % STG);
        COMPUTE(st);
    }

    // Epilogue
    float* Cb = WF32 ? (C + (long long)bz * sC) : nullptr;
    __nv_bfloat16* Hh = WHI ? (Chi + (long long)bz * sC) : nullptr;
    const float* Rb = RESID ? (resid + (long long)bz * sC) : nullptr;

    const int r0 = lane >> 2;
    const int c0 = (lane & 3) * 2;
#pragma unroll
    for (int mt = 0; mt < MT; mt++) {
#pragma unroll
        for (int nt = 0; nt < 8; nt++) {
            const int col = n0 + wn + nt * 8 + c0;
#pragma unroll
            for (int h = 0; h < 2; h++) {
                const long long row = m0 + wm + mt * 16 + r0 + h * 8;
                float v0 = acc[mt][nt][h * 2 + 0] * alpha;
                float v1 = acc[mt][nt][h * 2 + 1] * alpha;
                if (BIAS)  { v0 += bias[col]; v1 += bias[col + 1]; }
                if (RESID) {
                    v0 += Rb[row * N + col];
                    v1 += Rb[row * N + col + 1];
                }
                if (WF32) {
                    float2 o = {v0, v1};
                    *reinterpret_cast<float2*>(&Cb[row * N + col]) = o;
                }
                if (WHI) {
                    __nv_bfloat162 hp;
                    hp.x = __float2bfloat16(v0);
                    hp.y = __float2bfloat16(v1);
                    *reinterpret_cast<__nv_bfloat162*>(&Hh[row * N + col]) = hp;
                }
            }
        }
    }
}

// ---------------------------------------------------------------------------
// Merged input split: Q -> hi/lo, K -> hi   (one launch)
// ---------------------------------------------------------------------------
__global__ void __launch_bounds__(256)
split_inputs_kernel(const float* __restrict__ Q, const float* __restrict__ Kin,
                    __nv_bfloat16* __restrict__ Qhi, __nv_bfloat16* __restrict__ Qlo,
                    __nv_bfloat16* __restrict__ Khi, int nQ4, int nK4) {
    const int i = blockIdx.x * 256 + threadIdx.x;
    if (i < nQ4) {
        const float4 v = reinterpret_cast<const float4*>(Q)[i];
        __nv_bfloat16 h0 = __float2bfloat16(v.x), h1 = __float2bfloat16(v.y);
        __nv_bfloat16 h2 = __float2bfloat16(v.z), h3 = __float2bfloat16(v.w);
        __nv_bfloat162 hp0; hp0.x = h0; hp0.y = h1;
        __nv_bfloat162 hp1; hp1.x = h2; hp1.y = h3;
        __nv_bfloat162 lp0, lp1;
        lp0.x = __float2bfloat16(v.x - __bfloat162float(h0));
        lp0.y = __float2bfloat16(v.y - __bfloat162float(h1));
        lp1.x = __float2bfloat16(v.z - __bfloat162float(h2));
        lp1.y = __float2bfloat16(v.w - __bfloat162float(h3));
        reinterpret_cast<__nv_bfloat162*>(Qhi)[2 * i]     = hp0;
        reinterpret_cast<__nv_bfloat162*>(Qhi)[2 * i + 1] = hp1;
        reinterpret_cast<__nv_bfloat162*>(Qlo)[2 * i]     = lp0;
        reinterpret_cast<__nv_bfloat162*>(Qlo)[2 * i + 1] = lp1;
    } else {
        const int j = i - nQ4;
        if (j < nK4) {
            const float4 v = reinterpret_cast<const float4*>(Kin)[j];
            __nv_bfloat162 hp0, hp1;
            hp0.x = __float2bfloat16(v.x); hp0.y = __float2bfloat16(v.y);
            hp1.x = __float2bfloat16(v.z); hp1.y = __float2bfloat16(v.w);
            reinterpret_cast<__nv_bfloat162*>(Khi)[2 * j]     = hp0;
            reinterpret_cast<__nv_bfloat162*>(Khi)[2 * j + 1] = hp1;
        }
    }
}

// ---------------------------------------------------------------------------
// Merged weight split + mask probe (one launch).
// Segment k = i / nW4: 0=Wq(hi/lo), 1=Wk(hi), 2=Wv(hi), 3=Wp(hi).
// Block 0 additionally probes mask dtype.
// ---------------------------------------------------------------------------
__global__ void __launch_bounds__(256)
split_weights_probe_kernel(const float* __restrict__ Wq, const float* __restrict__ Wk,
                           const float* __restrict__ Wv, const float* __restrict__ Wp,
                           const unsigned char* __restrict__ mask,
                           __nv_bfloat16* __restrict__ Wqhi, __nv_bfloat16* __restrict__ Wqlo,
                           __nv_bfloat16* __restrict__ Wkhi, __nv_bfloat16* __restrict__ Wvhi,
                           __nv_bfloat16* __restrict__ Wphi, int nW4) {
    const int i = blockIdx.x * 256 + threadIdx.x;
    const int seg = i / nW4;
    const int j = i - seg * nW4;
    if (seg == 0) {
        const float4 v = reinterpret_cast<const float4*>(Wq)[j];
        __nv_bfloat16 h0 = __float2bfloat16(v.x), h1 = __float2bfloat16(v.y);
        __nv_bfloat16 h2 = __float2bfloat16(v.z), h3 = __float2bfloat16(v.w);
        __nv_bfloat162 hp0; hp0.x = h0; hp0.y = h1;
        __nv_bfloat162 hp1; hp1.x = h2; hp1.y = h3;
        __nv_bfloat162 lp0, lp1;
        lp0.x = __float2bfloat16(v.x - __bfloat162float(h0));
        lp0.y = __float2bfloat16(v.y - __bfloat162float(h1));
        lp1.x = __float2bfloat16(v.z - __bfloat162float(h2));
        lp1.y = __float2bfloat16(v.w - __bfloat162float(h3));
        reinterpret_cast<__nv_bfloat162*>(Wqhi)[2 * j]     = hp0;
        reinterpret_cast<__nv_bfloat162*>(Wqhi)[2 * j + 1] = hp1;
        reinterpret_cast<__nv_bfloat162*>(Wqlo)[2 * j]     = lp0;
        reinterpret_cast<__nv_bfloat162*>(Wqlo)[2 * j + 1] = lp1;
    } else if (seg < 4) {
        const float* W = (seg == 1) ? Wk : (seg == 2) ? Wv : Wp;
        __nv_bfloat16* D = (seg == 1) ? Wkhi : (seg == 2) ? Wvhi : Wphi;
        const float4 v = reinterpret_cast<const float4*>(W)[j];
        __nv_bfloat162 hp0, hp1;
        hp0.x = __float2bfloat16(v.x); hp0.y = __float2bfloat16(v.y);
        hp1.x = __float2bfloat16(v.z); hp1.y = __float2bfloat16(v.w);
        reinterpret_cast<__nv_bfloat162*>(D)[2 * j]     = hp0;
        reinterpret_cast<__nv_bfloat162*>(D)[2 * j + 1] = hp1;
    }
    // Mask dtype probe (block 0 only)
    if (blockIdx.x == 0) {
        __shared__ int found;
        if (threadIdx.x == 0) found = 0;
        __syncthreads();
        for (int t = threadIdx.x; t < 1024; t += 256)
            if (mask[t * 4 + 1] != 0) found = 1;
        __syncthreads();
        if (threadIdx.x == 0) g_mask4 = found ? 0 : 1;
    }
}

// ---------------------------------------------------------------------------
// Mask + softmax, in place on bf16 buffer
// ---------------------------------------------------------------------------
__global__ void __launch_bounds__(256)
softmax_mask_kernel(__nv_bfloat16* __restrict__ p, const void* __restrict__ mask) {
    const long long row = blockIdx.x;
    __nv_bfloat16* pr = p + row * SS;
    const long long mbase = row * SS;
    const int tid = threadIdx.x;
    const int is4 = g_mask4;

    float vals[8];
    float mx = -3.0e38f;
#pragma unroll
    for (int i = 0; i < 8; i++) {
        const int c = tid + (i << 8);
        float x = __bfloat162float(pr[c]);
        bool m;
        if (is4) m = reinterpret_cast<const unsigned int*>(mask)[mbase + c] != 0u;
        else     m = reinterpret_cast<const unsigned char*>(mask)[mbase + c] != 0;
        x = m ? -1e9f : x;
        vals[i] = x;
        mx = fmaxf(mx, x);
    }
    __shared__ float sred[8];
#pragma unroll
    for (int o = 16; o > 0; o >>= 1) mx = fmaxf(mx, __shfl_xor_sync(0xffffffffu, mx, o));
    if ((tid & 31) == 0) sred[tid >> 5] = mx;
    __syncthreads();
    float bm = sred[0];
#pragma unroll
    for (int w = 1; w < 8; w++) bm = fmaxf(bm, sred[w]);

    float sum = 0.f;
#pragma unroll
    for (int i = 0; i < 8; i++) {
        const float e = __expf(vals[i] - bm);
        vals[i] = e;
        sum += e;
    }
#pragma unroll
    for (int o = 16; o > 0; o >>= 1) sum += __shfl_xor_sync(0xffffffffu, sum, o);
    __shared__ float ssum[8];
    if ((tid & 31) == 0) ssum[tid >> 5] = sum;
    __syncthreads();
    float ts = 0.f;
#pragma unroll
    for (int w = 0; w < 8; w++) ts += ssum[w];

    const float inv = 1.0f / ts;
#pragma unroll
    for (int i = 0; i < 8; i++) {
        const int c = tid + (i << 8);
        pr[c] = __float2bfloat16(vals[i] * inv);
    }
}

// ---------------------------------------------------------------------------
// kernel_launch
// ---------------------------------------------------------------------------
extern "C" void kernel_launch(void* const* d_in, const int* in_sizes, int n_in,
                              void* d_out, int out_size) {
    const float* Q    = (const float*)d_in[0];
    const float* Kin  = (const float*)d_in[1];
    const void*  mask = (const void*)d_in[2];
    const float* Wq   = (const float*)d_in[3];
    const float* Wk   = (const float*)d_in[4];
    const float* Wv   = (const float*)d_in[5];
    const float* Wp   = (const float*)d_in[6];
    const float* bp   = (const float*)d_in[7];
    float* out        = (float*)d_out;

    __nv_bfloat16 *Qhi, *Qlo, *Khi, *Wqhi, *Wqlo, *Wkhi, *Wvhi, *Wphi2;
    __nv_bfloat16 *qhi, *khi, *vThi, *phi, *aohi;
    float *qf;
    cudaGetSymbolAddress((void**)&Qhi, g_Qhi);   cudaGetSymbolAddress((void**)&Qlo, g_Qlo);
    cudaGetSymbolAddress((void**)&Khi, g_Khi);
    cudaGetSymbolAddress((void**)&Wqhi, g_Wqhi); cudaGetSymbolAddress((void**)&Wqlo, g_Wqlo);
    cudaGetSymbolAddress((void**)&Wkhi, g_Wkhi);
    cudaGetSymbolAddress((void**)&Wvhi, g_Wvhi);
    cudaGetSymbolAddress((void**)&Wphi2, g_Wphi);
    cudaGetSymbolAddress((void**)&qf, g_qf);
    cudaGetSymbolAddress((void**)&qhi, g_qhi);
    cudaGetSymbolAddress((void**)&khi, g_khi);
    cudaGetSymbolAddress((void**)&vThi, g_vThi);
    cudaGetSymbolAddress((void**)&phi, g_phi);
    cudaGetSymbolAddress((void**)&aohi, g_aohi);

    // NPROD=1, BM=128, STG=3, 2 CTAs/SM: stage 36864, smem/CTA 110592
    constexpr int SM_1 = 3 * ((128 + 128) * PITCH);
    // NPROD=3, BM=128, STG=3, 1 CTA/SM: smem 221184
    constexpr int SM_3 = 3 * ((2 * 128 + 2 * 128) * PITCH);
    cudaFuncSetAttribute(hmma_gemm<128, 3, 3, 1, false, false, true,  true >,
                         cudaFuncAttributeMaxDynamicSharedMemorySize, SM_3);
    cudaFuncSetAttribute(hmma_gemm<128, 3, 1, 2, false, false, false, true >,
                         cudaFuncAttributeMaxDynamicSharedMemorySize, SM_1);
    cudaFuncSetAttribute(hmma_gemm<128, 3, 1, 2, true,  true,  true,  false>,
                         cudaFuncAttributeMaxDynamicSharedMemorySize, SM_1);

    const float scale = 0.04419417382415922f;  // 512^-0.5
    const long long sQKV = (long long)SS * EE;
    const long long sSC  = (long long)SS * SS;
    dim3 blk(256);
    const int nQ4 = MTOT * EE / 4, nW4 = EE * EE / 4;

    // 2 consolidated prep launches
    split_inputs_kernel<<<(2 * nQ4 + 255) / 256, blk>>>(Q, Kin, Qhi, Qlo, Khi, nQ4, nQ4);
    split_weights_probe_kernel<<<(4 * nW4 + 255) / 256, blk>>>(
        Wq, Wk, Wv, Wp, (const unsigned char*)mask,
        Wqhi, Wqlo, Wkhi, Wvhi, Wphi2, nW4);

    // q = Q Wq^T  (3-product; residual-critical) -> qf fp32 + qhi
    hmma_gemm<128, 3, 3, 1, false, false, true, true>
        <<<dim3(EE / 128, MTOT / 128, 1), blk, SM_3>>>(
        Qhi, Qlo, Wqhi, Wqlo, qf, qhi, MTOT, EE, EE, 0, 0, 0, 1.f, nullptr, nullptr);
    // k = K Wk^T  (1-product) -> khi
    hmma_gemm<128, 3, 1, 2, false, false, false, true>
        <<<dim3(EE / 128, MTOT / 128, 1), blk, SM_1>>>(
        Khi, nullptr, Wkhi, nullptr, nullptr, khi, MTOT, EE, EE,
        0, 0, 0, 1.f, nullptr, nullptr);
    // vT[b] = Wv K[b]^T  (1-product) -> vThi
    hmma_gemm<128, 3, 1, 2, false, false, false, true>
        <<<dim3(SS / 128, EE / 128, BB), blk, SM_1>>>(
        Wvhi, nullptr, Khi, nullptr, nullptr, vThi, EE, SS, EE,
        0, sQKV, (long long)EE * SS, 1.f, nullptr, nullptr);
    // scores[b] = scale * q[b] k[b]^T  (1-product) -> bf16 into phi
    hmma_gemm<128, 3, 1, 2, false, false, false, true>
        <<<dim3(SS / 128, SS / 128, BB), blk, SM_1>>>(
        qhi, nullptr, khi, nullptr, nullptr, phi, SS, SS, EE,
        sQKV, sQKV, sSC, scale, nullptr, nullptr);
    // mask + softmax in place on phi
    softmax_mask_kernel<<<BB * SS, blk>>>(phi, mask);
    // ao[b] = p[b] vT[b]^T  (1-product) -> aohi
    hmma_gemm<128, 3, 1, 2, false, false, false, true>
        <<<dim3(EE / 128, SS / 128, BB), blk, SM_1>>>(
        phi, nullptr, vThi, nullptr, nullptr, aohi, SS, EE, SS,
        sSC, (long long)EE * SS, sQKV, 1.f, nullptr, nullptr);
    // out = ao Wp^T + bp + q  (1-product + bias + residual)
    hmma_gemm<128, 3, 1, 2, true, true, true, false>
        <<<dim3(EE / 128, MTOT / 128, 1), blk, SM_1>>>(
        aohi, nullptr, Wphi2, nullptr, out, nullptr, MTOT, EE, EE,
        0, 0, 0, 1.f, bp, qf);
}

// round 10
// speedup vs baseline: 1.0123x; 1.0123x over previous
#include <cuda_runtime.h>
#include <cuda_bf16.h>
#include <cstdint>

#define BB 8
#define SS 2048
#define EE 512
#define MTOT (BB * SS)

// ---------------------------------------------------------------------------
// Scratch (__device__ globals; no allocation anywhere)
// ---------------------------------------------------------------------------
__device__ __nv_bfloat16 g_Qhi[(size_t)MTOT * EE], g_Qlo[(size_t)MTOT * EE];
__device__ __nv_bfloat16 g_Khi[(size_t)MTOT * EE];
__device__ __nv_bfloat16 g_Wqhi[EE * EE], g_Wqlo[EE * EE];
__device__ __nv_bfloat16 g_Wkhi[EE * EE];
__device__ __nv_bfloat16 g_Wvhi[EE * EE];
__device__ __nv_bfloat16 g_Wphi[EE * EE];
__device__ float         g_qf [(size_t)MTOT * EE];
__device__ __nv_bfloat16 g_qhi[(size_t)MTOT * EE];
__device__ __nv_bfloat16 g_khi[(size_t)MTOT * EE];
__device__ __nv_bfloat16 g_vThi[(size_t)BB * EE * SS];
__device__ __nv_bfloat16 g_phi[(size_t)BB * SS * SS];   // scores (bf16, masked) -> probs in place
__device__ __nv_bfloat16 g_aohi[(size_t)MTOT * EE];
__device__ int           g_mask4;

// ---------------------------------------------------------------------------
// Helpers (baseline PTX only; legal at .target sm_103)
// ---------------------------------------------------------------------------
__device__ __forceinline__ uint32_t smem_u32(const void* p) {
    uint32_t a;
    asm("{ .reg .u64 t; cvta.to.shared.u64 t, %1; cvt.u32.u64 %0, t; }"
        : "=r"(a) : "l"(p));
    return a;
}
__device__ __forceinline__ void cpasync16(uint32_t dst, const void* src) {
    asm volatile("cp.async.cg.shared.global [%0], [%1], 16;"
                 :: "r"(dst), "l"(src) : "memory");
}
#define CP_COMMIT() asm volatile("cp.async.commit_group;" ::: "memory")
#define CP_WAIT1()  asm volatile("cp.async.wait_group 1;" ::: "memory")
#define CP_WAIT0()  asm volatile("cp.async.wait_group 0;" ::: "memory")

__device__ __forceinline__ void ldsm4(uint32_t* r, uint32_t addr) {
    asm volatile("ldmatrix.sync.aligned.m8n8.x4.shared.b16 {%0,%1,%2,%3}, [%4];"
                 : "=r"(r[0]), "=r"(r[1]), "=r"(r[2]), "=r"(r[3]) : "r"(addr));
}
__device__ __forceinline__ void mma_bf16(float* d, const uint32_t* a, const uint32_t* b) {
    asm volatile(
        "mma.sync.aligned.m16n8k16.row.col.f32.bf16.bf16.f32 "
        "{%0,%1,%2,%3}, {%4,%5,%6,%7}, {%8,%9}, {%0,%1,%2,%3};"
        : "+f"(d[0]), "+f"(d[1]), "+f"(d[2]), "+f"(d[3])
        : "r"(a[0]), "r"(a[1]), "r"(a[2]), "r"(a[3]), "r"(b[0]), "r"(b[1]));
}

// SMEM rows: 64 bf16 (128 B data), pitch 144 B => conflict-free ldmatrix
#define PITCH    144
#define BTILE_B  (128 * PITCH)          // B tile is always 128 rows

// ---------------------------------------------------------------------------
// HMMA NT GEMM: C[M,N] = alpha * A[M,K] * B[N,K]^T, bf16, fp32 acc.
// NPROD=1: Ah*Bh.  NPROD=3: Ah*Bh + Ah*Bl + Al*Bh.
// Block BMx128, BK=64, 256 threads (8 warps: 4 m x 2 n), OCC CTAs/SM.
// STG-stage cp.async pipeline, one __syncthreads per K-iter (R8-proven form).
// MASKC: apply pad mask (-1e9) in the epilogue (scores GEMM only).
// ---------------------------------------------------------------------------
template <int BM, int STG, int NPROD, int OCC,
          bool BIAS, bool RESID, bool WF32, bool WHI, bool MASKC>
__global__ void __launch_bounds__(256, OCC)
hmma_gemm(const __nv_bfloat16* __restrict__ Ahi, const __nv_bfloat16* __restrict__ Alo,
          const __nv_bfloat16* __restrict__ Bhi, const __nv_bfloat16* __restrict__ Blo,
          float* __restrict__ C, __nv_bfloat16* __restrict__ Chi,
          int M, int N, int K,
          long long sA, long long sB, long long sC,
          float alpha, const float* __restrict__ bias, const float* __restrict__ resid,
          const void* __restrict__ maskp) {
    constexpr int MT      = BM / 64;             // m16 tiles per warp
    constexpr uint32_t ATILE = (uint32_t)BM * PITCH;
    constexpr uint32_t OFF_AL = ATILE;                                // NPROD==3
    constexpr uint32_t OFF_BH = (NPROD == 3) ? 2u * ATILE : ATILE;
    constexpr uint32_t OFF_BL = OFF_BH + BTILE_B;                     // NPROD==3
    constexpr uint32_t STAGE_B =
        ((NPROD == 3) ? 2u : 1u) * ATILE + ((NPROD == 3) ? 2u : 1u) * BTILE_B;

    extern __shared__ __align__(128) char smem[];
    const uint32_t sb = smem_u32(smem);

    const int tid  = threadIdx.x;
    const int wid  = tid >> 5;
    const int lane = tid & 31;
    const int bz   = blockIdx.z;
    const int m0   = blockIdx.y * BM;
    const int n0   = blockIdx.x * 128;

    const __nv_bfloat16* Ah = Ahi + (long long)bz * sA;
    const __nv_bfloat16* Al = (NPROD == 3) ? (Alo + (long long)bz * sA) : nullptr;
    const __nv_bfloat16* Bh = Bhi + (long long)bz * sB;
    const __nv_bfloat16* Bl = (NPROD == 3) ? (Blo + (long long)bz * sB) : nullptr;

    const int nkt = K >> 6;

    auto FETCH = [&](int kt, int st) {
        const uint32_t base = sb + (uint32_t)st * STAGE_B;
#pragma unroll
        for (int t = 0; t < BM / 32; t++) {
            const int c   = tid + t * 256;
            const int row = c >> 3;
            const int cp  = c & 7;
            const uint32_t doff = row * PITCH + cp * 16;
            const long long ga = (long long)(m0 + row) * K + (kt << 6) + cp * 8;
            cpasync16(base + doff, Ah + ga);
            if (NPROD == 3) cpasync16(base + OFF_AL + doff, Al + ga);
        }
#pragma unroll
        for (int t = 0; t < 4; t++) {
            const int c   = tid + t * 256;
            const int row = c >> 3;
            const int cp  = c & 7;
            const uint32_t doff = row * PITCH + cp * 16;
            const long long gb = (long long)(n0 + row) * K + (kt << 6) + cp * 8;
            cpasync16(base + OFF_BH + doff, Bh + gb);
            if (NPROD == 3) cpasync16(base + OFF_BL + doff, Bl + gb);
        }
        CP_COMMIT();
    };

    float acc[MT][8][4];
#pragma unroll
    for (int mt = 0; mt < MT; mt++)
#pragma unroll
        for (int nt = 0; nt < 8; nt++)
#pragma unroll
            for (int j = 0; j < 4; j++) acc[mt][nt][j] = 0.f;

    const int wm = (wid & 3) * (BM / 4);   // warp m offset
    const int wn = (wid >> 2) * 64;        // warp n offset
    const int i8 = lane & 7;
    const uint32_t a_off = (uint32_t)(i8 + ((lane >> 3) & 1) * 8) * PITCH + (lane >> 4) * 16;
    const uint32_t b_off = (uint32_t)(i8 + ((lane >> 4) & 1) * 8) * PITCH + ((lane >> 3) & 1) * 16;

    auto COMPUTE = [&](int st) {
        const uint32_t base = sb + (uint32_t)st * STAGE_B;
        const uint32_t aAh = base + (uint32_t)wm * PITCH + a_off;
        const uint32_t aBh = base + OFF_BH + (uint32_t)wn * PITCH + b_off;
        const uint32_t aBl = base + OFF_BL + (uint32_t)wn * PITCH + b_off;
#pragma unroll
        for (int ks = 0; ks < 4; ks++) {
            uint32_t ah[MT][4], al[MT][4], bh[4][4], bl[4][4];
#pragma unroll
            for (int mt = 0; mt < MT; mt++) {
                ldsm4(ah[mt], aAh + mt * 16 * PITCH + ks * 32);
                if (NPROD == 3) ldsm4(al[mt], aAh + OFF_AL + mt * 16 * PITCH + ks * 32);
            }
#pragma unroll
            for (int nt = 0; nt < 4; nt++) {
                ldsm4(bh[nt], aBh + nt * 16 * PITCH + ks * 32);
                if (NPROD == 3) ldsm4(bl[nt], aBl + nt * 16 * PITCH + ks * 32);
            }
#pragma unroll
            for (int mt = 0; mt < MT; mt++)
#pragma unroll
                for (int nt = 0; nt < 8; nt++)
                    mma_bf16(acc[mt][nt], ah[mt], &bh[nt >> 1][(nt & 1) * 2]);
            if (NPROD == 3) {
#pragma unroll
                for (int mt = 0; mt < MT; mt++)
#pragma unroll
                    for (int nt = 0; nt < 8; nt++)
                        mma_bf16(acc[mt][nt], ah[mt], &bl[nt >> 1][(nt & 1) * 2]);
#pragma unroll
                for (int mt = 0; mt < MT; mt++)
#pragma unroll
                    for (int nt = 0; nt < 8; nt++)
                        mma_bf16(acc[mt][nt], al[mt], &bh[nt >> 1][(nt & 1) * 2]);
            }
        }
    };

    FETCH(0, 0);
    FETCH(1, 1);

    for (int kt = 0; kt < nkt; kt++) {
        const int st  = kt % STG;
        const int rem = nkt - kt - 1;
        if (rem >= 1) { CP_WAIT1(); } else { CP_WAIT0(); }
        __syncthreads();
        COMPUTE(st);
        if (kt + STG - 1 < nkt) FETCH(kt + STG - 1, (kt + STG - 1) % STG);
    }

    // Epilogue
    float* Cb = WF32 ? (C + (long long)bz * sC) : nullptr;
    __nv_bfloat16* Hh = WHI ? (Chi + (long long)bz * sC) : nullptr;
    const float* Rb = RESID ? (resid + (long long)bz * sC) : nullptr;
    const int m4 = MASKC ? g_mask4 : 0;

    const int r0 = lane >> 2;
    const int c0 = (lane & 3) * 2;
#pragma unroll
    for (int mt = 0; mt < MT; mt++) {
#pragma unroll
        for (int nt = 0; nt < 8; nt++) {
            const int col = n0 + wn + nt * 8 + c0;
#pragma unroll
            for (int h = 0; h < 2; h++) {
                const long long row = m0 + wm + mt * 16 + r0 + h * 8;
                float v0 = acc[mt][nt][h * 2 + 0] * alpha;
                float v1 = acc[mt][nt][h * 2 + 1] * alpha;
                if (BIAS)  { v0 += bias[col]; v1 += bias[col + 1]; }
                if (RESID) {
                    v0 += Rb[row * N + col];
                    v1 += Rb[row * N + col + 1];
                }
                if (MASKC) {
                    const long long mo = (long long)bz * sC + row * N + col;
                    bool mk0, mk1;
                    if (m4) {
                        const uint2 mv = *reinterpret_cast<const uint2*>(
                            reinterpret_cast<const unsigned int*>(maskp) + mo);
                        mk0 = mv.x != 0u; mk1 = mv.y != 0u;
                    } else {
                        const unsigned char* mp =
                            reinterpret_cast<const unsigned char*>(maskp) + mo;
                        mk0 = mp[0] != 0; mk1 = mp[1] != 0;
                    }
                    if (mk0) v0 = -1e9f;
                    if (mk1) v1 = -1e9f;
                }
                if (WF32) {
                    float2 o = {v0, v1};
                    *reinterpret_cast<float2*>(&Cb[row * N + col]) = o;
                }
                if (WHI) {
                    __nv_bfloat162 hp;
                    hp.x = __float2bfloat16(v0);
                    hp.y = __float2bfloat16(v1);
                    *reinterpret_cast<__nv_bfloat162*>(&Hh[row * N + col]) = hp;
                }
            }
        }
    }
}

// ---------------------------------------------------------------------------
// Merged input split: Q -> hi/lo, K -> hi   (one launch)
// ---------------------------------------------------------------------------
__global__ void __launch_bounds__(256)
split_inputs_kernel(const float* __restrict__ Q, const float* __restrict__ Kin,
                    __nv_bfloat16* __restrict__ Qhi, __nv_bfloat16* __restrict__ Qlo,
                    __nv_bfloat16* __restrict__ Khi, int nQ4, int nK4) {
    const int i = blockIdx.x * 256 + threadIdx.x;
    if (i < nQ4) {
        const float4 v = reinterpret_cast<const float4*>(Q)[i];
        __nv_bfloat16 h0 = __float2bfloat16(v.x), h1 = __float2bfloat16(v.y);
        __nv_bfloat16 h2 = __float2bfloat16(v.z), h3 = __float2bfloat16(v.w);
        __nv_bfloat162 hp0; hp0.x = h0; hp0.y = h1;
        __nv_bfloat162 hp1; hp1.x = h2; hp1.y = h3;
        __nv_bfloat162 lp0, lp1;
        lp0.x = __float2bfloat16(v.x - __bfloat162float(h0));
        lp0.y = __float2bfloat16(v.y - __bfloat162float(h1));
        lp1.x = __float2bfloat16(v.z - __bfloat162float(h2));
        lp1.y = __float2bfloat16(v.w - __bfloat162float(h3));
        reinterpret_cast<__nv_bfloat162*>(Qhi)[2 * i]     = hp0;
        reinterpret_cast<__nv_bfloat162*>(Qhi)[2 * i + 1] = hp1;
        reinterpret_cast<__nv_bfloat162*>(Qlo)[2 * i]     = lp0;
        reinterpret_cast<__nv_bfloat162*>(Qlo)[2 * i + 1] = lp1;
    } else {
        const int j = i - nQ4;
        if (j < nK4) {
            const float4 v = reinterpret_cast<const float4*>(Kin)[j];
            __nv_bfloat162 hp0, hp1;
            hp0.x = __float2bfloat16(v.x); hp0.y = __float2bfloat16(v.y);
            hp1.x = __float2bfloat16(v.z); hp1.y = __float2bfloat16(v.w);
            reinterpret_cast<__nv_bfloat162*>(Khi)[2 * j]     = hp0;
            reinterpret_cast<__nv_bfloat162*>(Khi)[2 * j + 1] = hp1;
        }
    }
}

// ---------------------------------------------------------------------------
// Merged weight split + mask probe (one launch).
// ---------------------------------------------------------------------------
__global__ void __launch_bounds__(256)
split_weights_probe_kernel(const float* __restrict__ Wq, const float* __restrict__ Wk,
                           const float* __restrict__ Wv, const float* __restrict__ Wp,
                           const unsigned char* __restrict__ mask,
                           __nv_bfloat16* __restrict__ Wqhi, __nv_bfloat16* __restrict__ Wqlo,
                           __nv_bfloat16* __restrict__ Wkhi, __nv_bfloat16* __restrict__ Wvhi,
                           __nv_bfloat16* __restrict__ Wphi, int nW4) {
    const int i = blockIdx.x * 256 + threadIdx.x;
    const int seg = i / nW4;
    const int j = i - seg * nW4;
    if (seg == 0) {
        const float4 v = reinterpret_cast<const float4*>(Wq)[j];
        __nv_bfloat16 h0 = __float2bfloat16(v.x), h1 = __float2bfloat16(v.y);
        __nv_bfloat16 h2 = __float2bfloat16(v.z), h3 = __float2bfloat16(v.w);
        __nv_bfloat162 hp0; hp0.x = h0; hp0.y = h1;
        __nv_bfloat162 hp1; hp1.x = h2; hp1.y = h3;
        __nv_bfloat162 lp0, lp1;
        lp0.x = __float2bfloat16(v.x - __bfloat162float(h0));
        lp0.y = __float2bfloat16(v.y - __bfloat162float(h1));
        lp1.x = __float2bfloat16(v.z - __bfloat162float(h2));
        lp1.y = __float2bfloat16(v.w - __bfloat162float(h3));
        reinterpret_cast<__nv_bfloat162*>(Wqhi)[2 * j]     = hp0;
        reinterpret_cast<__nv_bfloat162*>(Wqhi)[2 * j + 1] = hp1;
        reinterpret_cast<__nv_bfloat162*>(Wqlo)[2 * j]     = lp0;
        reinterpret_cast<__nv_bfloat162*>(Wqlo)[2 * j + 1] = lp1;
    } else if (seg < 4) {
        const float* W = (seg == 1) ? Wk : (seg == 2) ? Wv : Wp;
        __nv_bfloat16* D = (seg == 1) ? Wkhi : (seg == 2) ? Wvhi : Wphi;
        const float4 v = reinterpret_cast<const float4*>(W)[j];
        __nv_bfloat162 hp0, hp1;
        hp0.x = __float2bfloat16(v.x); hp0.y = __float2bfloat16(v.y);
        hp1.x = __float2bfloat16(v.z); hp1.y = __float2bfloat16(v.w);
        reinterpret_cast<__nv_bfloat162*>(D)[2 * j]     = hp0;
        reinterpret_cast<__nv_bfloat162*>(D)[2 * j + 1] = hp1;
    }
    if (blockIdx.x == 0) {
        __shared__ int found;
        if (threadIdx.x == 0) found = 0;
        __syncthreads();
        for (int t = threadIdx.x; t < 1024; t += 256)
            if (mask[t * 4 + 1] != 0) found = 1;
        __syncthreads();
        if (threadIdx.x == 0) g_mask4 = found ? 0 : 1;
    }
}

// ---------------------------------------------------------------------------
// Softmax, in place on bf16 buffer (mask already applied in GEMM epilogue)
// ---------------------------------------------------------------------------
__global__ void __launch_bounds__(256)
softmax_kernel(__nv_bfloat16* __restrict__ p) {
    const long long row = blockIdx.x;
    __nv_bfloat16* pr = p + row * SS;
    const int tid = threadIdx.x;

    float vals[8];
    float mx = -3.0e38f;
#pragma unroll
    for (int i = 0; i < 8; i += 2) {
        const int c = tid * 2 + (i << 8);           // 2 contiguous per thread
        const __nv_bfloat162 x2 = *reinterpret_cast<const __nv_bfloat162*>(&pr[c]);
        vals[i]     = __bfloat162float(x2.x);
        vals[i + 1] = __bfloat162float(x2.y);
        mx = fmaxf(mx, fmaxf(vals[i], vals[i + 1]));
    }
    __shared__ float sred[8];
#pragma unroll
    for (int o = 16; o > 0; o >>= 1) mx = fmaxf(mx, __shfl_xor_sync(0xffffffffu, mx, o));
    if ((tid & 31) == 0) sred[tid >> 5] = mx;
    __syncthreads();
    float bm = sred[0];
#pragma unroll
    for (int w = 1; w < 8; w++) bm = fmaxf(bm, sred[w]);

    float sum = 0.f;
#pragma unroll
    for (int i = 0; i < 8; i++) {
        const float e = __expf(vals[i] - bm);
        vals[i] = e;
        sum += e;
    }
#pragma unroll
    for (int o = 16; o > 0; o >>= 1) sum += __shfl_xor_sync(0xffffffffu, sum, o);
    __shared__ float ssum[8];
    if ((tid & 31) == 0) ssum[tid >> 5] = sum;
    __syncthreads();
    float ts = 0.f;
#pragma unroll
    for (int w = 0; w < 8; w++) ts += ssum[w];

    const float inv = 1.0f / ts;
#pragma unroll
    for (int i = 0; i < 8; i += 2) {
        const int c = tid * 2 + (i << 8);
        __nv_bfloat162 o2;
        o2.x = __float2bfloat16(vals[i] * inv);
        o2.y = __float2bfloat16(vals[i + 1] * inv);
        *reinterpret_cast<__nv_bfloat162*>(&pr[c]) = o2;
    }
}

// ---------------------------------------------------------------------------
// kernel_launch
// ---------------------------------------------------------------------------
extern "C" void kernel_launch(void* const* d_in, const int* in_sizes, int n_in,
                              void* d_out, int out_size) {
    const float* Q    = (const float*)d_in[0];
    const float* Kin  = (const float*)d_in[1];
    const void*  mask = (const void*)d_in[2];
    const float* Wq   = (const float*)d_in[3];
    const float* Wk   = (const float*)d_in[4];
    const float* Wv   = (const float*)d_in[5];
    const float* Wp   = (const float*)d_in[6];
    const float* bp   = (const float*)d_in[7];
    float* out        = (float*)d_out;

    __nv_bfloat16 *Qhi, *Qlo, *Khi, *Wqhi, *Wqlo, *Wkhi, *Wvhi, *Wphi2;
    __nv_bfloat16 *qhi, *khi, *vThi, *phi, *aohi;
    float *qf;
    cudaGetSymbolAddress((void**)&Qhi, g_Qhi);   cudaGetSymbolAddress((void**)&Qlo, g_Qlo);
    cudaGetSymbolAddress((void**)&Khi, g_Khi);
    cudaGetSymbolAddress((void**)&Wqhi, g_Wqhi); cudaGetSymbolAddress((void**)&Wqlo, g_Wqlo);
    cudaGetSymbolAddress((void**)&Wkhi, g_Wkhi);
    cudaGetSymbolAddress((void**)&Wvhi, g_Wvhi);
    cudaGetSymbolAddress((void**)&Wphi2, g_Wphi);
    cudaGetSymbolAddress((void**)&qf, g_qf);
    cudaGetSymbolAddress((void**)&qhi, g_qhi);
    cudaGetSymbolAddress((void**)&khi, g_khi);
    cudaGetSymbolAddress((void**)&vThi, g_vThi);
    cudaGetSymbolAddress((void**)&phi, g_phi);
    cudaGetSymbolAddress((void**)&aohi, g_aohi);

    constexpr int SM_1 = 3 * ((128 + 128) * PITCH);          // 110592/CTA, 2 CTA/SM
    constexpr int SM_3 = 3 * ((2 * 128 + 2 * 128) * PITCH);  // 221184, 1 CTA/SM
    cudaFuncSetAttribute(hmma_gemm<128, 3, 3, 1, false, false, true,  true,  false>,
                         cudaFuncAttributeMaxDynamicSharedMemorySize, SM_3);
    cudaFuncSetAttribute(hmma_gemm<128, 3, 1, 2, false, false, false, true,  false>,
                         cudaFuncAttributeMaxDynamicSharedMemorySize, SM_1);
    cudaFuncSetAttribute(hmma_gemm<128, 3, 1, 2, false, false, false, true,  true >,
                         cudaFuncAttributeMaxDynamicSharedMemorySize, SM_1);
    cudaFuncSetAttribute(hmma_gemm<128, 3, 1, 2, true,  true,  true,  false, false>,
                         cudaFuncAttributeMaxDynamicSharedMemorySize, SM_1);

    const float scale = 0.04419417382415922f;  // 512^-0.5
    const long long sQKV = (long long)SS * EE;
    const long long sSC  = (long long)SS * SS;
    dim3 blk(256);
    const int nQ4 = MTOT * EE / 4, nW4 = EE * EE / 4;

    // 2 consolidated prep launches
    split_inputs_kernel<<<(2 * nQ4 + 255) / 256, blk>>>(Q, Kin, Qhi, Qlo, Khi, nQ4, nQ4);
    split_weights_probe_kernel<<<(4 * nW4 + 255) / 256, blk>>>(
        Wq, Wk, Wv, Wp, (const unsigned char*)mask,
        Wqhi, Wqlo, Wkhi, Wvhi, Wphi2, nW4);

    // q = Q Wq^T  (3-product; residual-critical) -> qf fp32 + qhi
    hmma_gemm<128, 3, 3, 1, false, false, true, true, false>
        <<<dim3(EE / 128, MTOT / 128, 1), blk, SM_3>>>(
        Qhi, Qlo, Wqhi, Wqlo, qf, qhi, MTOT, EE, EE, 0, 0, 0, 1.f,
        nullptr, nullptr, nullptr);
    // k = K Wk^T  (1-product) -> khi
    hmma_gemm<128, 3, 1, 2, false, false, false, true, false>
        <<<dim3(EE / 128, MTOT / 128, 1), blk, SM_1>>>(
        Khi, nullptr, Wkhi, nullptr, nullptr, khi, MTOT, EE, EE,
        0, 0, 0, 1.f, nullptr, nullptr, nullptr);
    // vT[b] = Wv K[b]^T  (1-product) -> vThi
    hmma_gemm<128, 3, 1, 2, false, false, false, true, false>
        <<<dim3(SS / 128, EE / 128, BB), blk, SM_1>>>(
        Wvhi, nullptr, Khi, nullptr, nullptr, vThi, EE, SS, EE,
        0, sQKV, (long long)EE * SS, 1.f, nullptr, nullptr, nullptr);
    // scores[b] = scale * q[b] k[b]^T, mask applied in epilogue -> bf16 phi
    hmma_gemm<128, 3, 1, 2, false, false, false, true, true>
        <<<dim3(SS / 128, SS / 128, BB), blk, SM_1>>>(
        qhi, nullptr, khi, nullptr, nullptr, phi, SS, SS, EE,
        sQKV, sQKV, sSC, scale, nullptr, nullptr, mask);
    // softmax in place on phi (mask pre-applied)
    softmax_kernel<<<BB * SS, blk>>>(phi);
    // ao[b] = p[b] vT[b]^T  (1-product) -> aohi
    hmma_gemm<128, 3, 1, 2, false, false, false, true, false>
        <<<dim3(EE / 128, SS / 128, BB), blk, SM_1>>>(
        phi, nullptr, vThi, nullptr, nullptr, aohi, SS, EE, SS,
        sSC, (long long)EE * SS, sQKV, 1.f, nullptr, nullptr, nullptr);
    // out = ao Wp^T + bp + q  (1-product + bias + residual)
    hmma_gemm<128, 3, 1, 2, true, true, true, false, false>
        <<<dim3(EE / 128, MTOT / 128, 1), blk, SM_1>>>(
        aohi, nullptr, Wphi2, nullptr, out, nullptr, MTOT, EE, EE,
        0, 0, 0, 1.f, bp, qf, nullptr);
}

// round 11
// speedup vs baseline: 1.1394x; 1.1255x over previous
#include <cuda_runtime.h>
#include <cuda_bf16.h>
#include <cstdint>

#define BB 8
#define SS 2048
#define EE 512
#define MTOT (BB * SS)

// ---------------------------------------------------------------------------
// Scratch (__device__ globals; no allocation anywhere)
// ---------------------------------------------------------------------------
__device__ __nv_bfloat16 g_Qhi[(size_t)MTOT * EE], g_Qlo[(size_t)MTOT * EE];
__device__ __nv_bfloat16 g_Khi[(size_t)MTOT * EE];
__device__ __nv_bfloat16 g_Wqhi[EE * EE], g_Wqlo[EE * EE];
__device__ __nv_bfloat16 g_Wkhi[EE * EE];
__device__ __nv_bfloat16 g_Wvhi[EE * EE];
__device__ __nv_bfloat16 g_Wphi[EE * EE];
__device__ float         g_qf [(size_t)MTOT * EE];
__device__ __nv_bfloat16 g_qhi[(size_t)MTOT * EE];
__device__ __nv_bfloat16 g_khi[(size_t)MTOT * EE];
__device__ __nv_bfloat16 g_vThi[(size_t)BB * EE * SS];
__device__ __nv_bfloat16 g_phi[(size_t)BB * SS * SS];   // scores (bf16) -> probs in place
__device__ __nv_bfloat16 g_aohi[(size_t)MTOT * EE];
__device__ int           g_mask4;

// ---------------------------------------------------------------------------
// Helpers (baseline PTX only; legal at .target sm_103)
// ---------------------------------------------------------------------------
__device__ __forceinline__ uint32_t smem_u32(const void* p) {
    uint32_t a;
    asm("{ .reg .u64 t; cvta.to.shared.u64 t, %1; cvt.u32.u64 %0, t; }"
        : "=r"(a) : "l"(p));
    return a;
}
__device__ __forceinline__ void cpasync16(uint32_t dst, const void* src) {
    asm volatile("cp.async.cg.shared.global [%0], [%1], 16;"
                 :: "r"(dst), "l"(src) : "memory");
}
#define CP_COMMIT() asm volatile("cp.async.commit_group;" ::: "memory")
#define CP_WAIT1()  asm volatile("cp.async.wait_group 1;" ::: "memory")
#define CP_WAIT0()  asm volatile("cp.async.wait_group 0;" ::: "memory")

__device__ __forceinline__ void ldsm4(uint32_t* r, uint32_t addr) {
    asm volatile("ldmatrix.sync.aligned.m8n8.x4.shared.b16 {%0,%1,%2,%3}, [%4];"
                 : "=r"(r[0]), "=r"(r[1]), "=r"(r[2]), "=r"(r[3]) : "r"(addr));
}
__device__ __forceinline__ void mma_bf16(float* d, const uint32_t* a, const uint32_t* b) {
    asm volatile(
        "mma.sync.aligned.m16n8k16.row.col.f32.bf16.bf16.f32 "
        "{%0,%1,%2,%3}, {%4,%5,%6,%7}, {%8,%9}, {%0,%1,%2,%3};"
        : "+f"(d[0]), "+f"(d[1]), "+f"(d[2]), "+f"(d[3])
        : "r"(a[0]), "r"(a[1]), "r"(a[2]), "r"(a[3]), "r"(b[0]), "r"(b[1]));
}

// SMEM rows: 64 bf16 (128 B data), pitch 144 B => conflict-free ldmatrix
#define PITCH    144
#define BTILE_B  (128 * PITCH)          // B tile is always 128 rows

// ---------------------------------------------------------------------------
// HMMA NT GEMM: C[M,N] = alpha * A[M,K] * B[N,K]^T, bf16, fp32 acc.
// NPROD=1: Ah*Bh.  NPROD=3: Ah*Bh + Ah*Bl + Al*Bh.
// Block BMx128, BK=64, 256 threads (8 warps: 4 m x 2 n), OCC CTAs/SM.
// STG-stage cp.async pipeline, one __syncthreads per K-iter (R8-proven form).
// ---------------------------------------------------------------------------
template <int BM, int STG, int NPROD, int OCC,
          bool BIAS, bool RESID, bool WF32, bool WHI>
__global__ void __launch_bounds__(256, OCC)
hmma_gemm(const __nv_bfloat16* __restrict__ Ahi, const __nv_bfloat16* __restrict__ Alo,
          const __nv_bfloat16* __restrict__ Bhi, const __nv_bfloat16* __restrict__ Blo,
          float* __restrict__ C, __nv_bfloat16* __restrict__ Chi,
          int M, int N, int K,
          long long sA, long long sB, long long sC,
          float alpha, const float* __restrict__ bias, const float* __restrict__ resid) {
    constexpr int MT      = BM / 64;             // m16 tiles per warp
    constexpr uint32_t ATILE = (uint32_t)BM * PITCH;
    constexpr uint32_t OFF_AL = ATILE;                                // NPROD==3
    constexpr uint32_t OFF_BH = (NPROD == 3) ? 2u * ATILE : ATILE;
    constexpr uint32_t OFF_BL = OFF_BH + BTILE_B;                     // NPROD==3
    constexpr uint32_t STAGE_B =
        ((NPROD == 3) ? 2u : 1u) * ATILE + ((NPROD == 3) ? 2u : 1u) * BTILE_B;

    extern __shared__ __align__(128) char smem[];
    const uint32_t sb = smem_u32(smem);

    const int tid  = threadIdx.x;
    const int wid  = tid >> 5;
    const int lane = tid & 31;
    const int bz   = blockIdx.z;
    const int m0   = blockIdx.y * BM;
    const int n0   = blockIdx.x * 128;

    const __nv_bfloat16* Ah = Ahi + (long long)bz * sA;
    const __nv_bfloat16* Al = (NPROD == 3) ? (Alo + (long long)bz * sA) : nullptr;
    const __nv_bfloat16* Bh = Bhi + (long long)bz * sB;
    const __nv_bfloat16* Bl = (NPROD == 3) ? (Blo + (long long)bz * sB) : nullptr;

    const int nkt = K >> 6;

    auto FETCH = [&](int kt, int st) {
        const uint32_t base = sb + (uint32_t)st * STAGE_B;
#pragma unroll
        for (int t = 0; t < BM / 32; t++) {
            const int c   = tid + t * 256;
            const int row = c >> 3;
            const int cp  = c & 7;
            const uint32_t doff = row * PITCH + cp * 16;
            const long long ga = (long long)(m0 + row) * K + (kt << 6) + cp * 8;
            cpasync16(base + doff, Ah + ga);
            if (NPROD == 3) cpasync16(base + OFF_AL + doff, Al + ga);
        }
#pragma unroll
        for (int t = 0; t < 4; t++) {
            const int c   = tid + t * 256;
            const int row = c >> 3;
            const int cp  = c & 7;
            const uint32_t doff = row * PITCH + cp * 16;
            const long long gb = (long long)(n0 + row) * K + (kt << 6) + cp * 8;
            cpasync16(base + OFF_BH + doff, Bh + gb);
            if (NPROD == 3) cpasync16(base + OFF_BL + doff, Bl + gb);
        }
        CP_COMMIT();
    };

    float acc[MT][8][4];
#pragma unroll
    for (int mt = 0; mt < MT; mt++)
#pragma unroll
        for (int nt = 0; nt < 8; nt++)
#pragma unroll
            for (int j = 0; j < 4; j++) acc[mt][nt][j] = 0.f;

    const int wm = (wid & 3) * (BM / 4);   // warp m offset
    const int wn = (wid >> 2) * 64;        // warp n offset
    const int i8 = lane & 7;
    const uint32_t a_off = (uint32_t)(i8 + ((lane >> 3) & 1) * 8) * PITCH + (lane >> 4) * 16;
    const uint32_t b_off = (uint32_t)(i8 + ((lane >> 4) & 1) * 8) * PITCH + ((lane >> 3) & 1) * 16;

    auto COMPUTE = [&](int st) {
        const uint32_t base = sb + (uint32_t)st * STAGE_B;
        const uint32_t aAh = base + (uint32_t)wm * PITCH + a_off;
        const uint32_t aBh = base + OFF_BH + (uint32_t)wn * PITCH + b_off;
        const uint32_t aBl = base + OFF_BL + (uint32_t)wn * PITCH + b_off;
#pragma unroll
        for (int ks = 0; ks < 4; ks++) {
            uint32_t ah[MT][4], al[MT][4], bh[4][4], bl[4][4];
#pragma unroll
            for (int mt = 0; mt < MT; mt++) {
                ldsm4(ah[mt], aAh + mt * 16 * PITCH + ks * 32);
                if (NPROD == 3) ldsm4(al[mt], aAh + OFF_AL + mt * 16 * PITCH + ks * 32);
            }
#pragma unroll
            for (int nt = 0; nt < 4; nt++) {
                ldsm4(bh[nt], aBh + nt * 16 * PITCH + ks * 32);
                if (NPROD == 3) ldsm4(bl[nt], aBl + nt * 16 * PITCH + ks * 32);
            }
#pragma unroll
            for (int mt = 0; mt < MT; mt++)
#pragma unroll
                for (int nt = 0; nt < 8; nt++)
                    mma_bf16(acc[mt][nt], ah[mt], &bh[nt >> 1][(nt & 1) * 2]);
            if (NPROD == 3) {
#pragma unroll
                for (int mt = 0; mt < MT; mt++)
#pragma unroll
                    for (int nt = 0; nt < 8; nt++)
                        mma_bf16(acc[mt][nt], ah[mt], &bl[nt >> 1][(nt & 1) * 2]);
#pragma unroll
                for (int mt = 0; mt < MT; mt++)
#pragma unroll
                    for (int nt = 0; nt < 8; nt++)
                        mma_bf16(acc[mt][nt], al[mt], &bh[nt >> 1][(nt & 1) * 2]);
            }
        }
    };

    FETCH(0, 0);
    FETCH(1, 1);

    for (int kt = 0; kt < nkt; kt++) {
        const int st  = kt % STG;
        const int rem = nkt - kt - 1;
        if (rem >= 1) { CP_WAIT1(); } else { CP_WAIT0(); }
        __syncthreads();
        COMPUTE(st);
        if (kt + STG - 1 < nkt) FETCH(kt + STG - 1, (kt + STG - 1) % STG);
    }

    // Epilogue
    float* Cb = WF32 ? (C + (long long)bz * sC) : nullptr;
    __nv_bfloat16* Hh = WHI ? (Chi + (long long)bz * sC) : nullptr;
    const float* Rb = RESID ? (resid + (long long)bz * sC) : nullptr;

    const int r0 = lane >> 2;
    const int c0 = (lane & 3) * 2;
#pragma unroll
    for (int mt = 0; mt < MT; mt++) {
#pragma unroll
        for (int nt = 0; nt < 8; nt++) {
            const int col = n0 + wn + nt * 8 + c0;
#pragma unroll
            for (int h = 0; h < 2; h++) {
                const long long row = m0 + wm + mt * 16 + r0 + h * 8;
                float v0 = acc[mt][nt][h * 2 + 0] * alpha;
                float v1 = acc[mt][nt][h * 2 + 1] * alpha;
                if (BIAS)  { v0 += bias[col]; v1 += bias[col + 1]; }
                if (RESID) {
                    v0 += Rb[row * N + col];
                    v1 += Rb[row * N + col + 1];
                }
                if (WF32) {
                    float2 o = {v0, v1};
                    *reinterpret_cast<float2*>(&Cb[row * N + col]) = o;
                }
                if (WHI) {
                    __nv_bfloat162 hp;
                    hp.x = __float2bfloat16(v0);
                    hp.y = __float2bfloat16(v1);
                    *reinterpret_cast<__nv_bfloat162*>(&Hh[row * N + col]) = hp;
                }
            }
        }
    }
}

// ---------------------------------------------------------------------------
// Merged input split: Q -> hi/lo, K -> hi   (one launch)
// ---------------------------------------------------------------------------
__global__ void __launch_bounds__(256)
split_inputs_kernel(const float* __restrict__ Q, const float* __restrict__ Kin,
                    __nv_bfloat16* __restrict__ Qhi, __nv_bfloat16* __restrict__ Qlo,
                    __nv_bfloat16* __restrict__ Khi, int nQ4, int nK4) {
    const int i = blockIdx.x * 256 + threadIdx.x;
    if (i < nQ4) {
        const float4 v = reinterpret_cast<const float4*>(Q)[i];
        __nv_bfloat16 h0 = __float2bfloat16(v.x), h1 = __float2bfloat16(v.y);
        __nv_bfloat16 h2 = __float2bfloat16(v.z), h3 = __float2bfloat16(v.w);
        __nv_bfloat162 hp0; hp0.x = h0; hp0.y = h1;
        __nv_bfloat162 hp1; hp1.x = h2; hp1.y = h3;
        __nv_bfloat162 lp0, lp1;
        lp0.x = __float2bfloat16(v.x - __bfloat162float(h0));
        lp0.y = __float2bfloat16(v.y - __bfloat162float(h1));
        lp1.x = __float2bfloat16(v.z - __bfloat162float(h2));
        lp1.y = __float2bfloat16(v.w - __bfloat162float(h3));
        reinterpret_cast<__nv_bfloat162*>(Qhi)[2 * i]     = hp0;
        reinterpret_cast<__nv_bfloat162*>(Qhi)[2 * i + 1] = hp1;
        reinterpret_cast<__nv_bfloat162*>(Qlo)[2 * i]     = lp0;
        reinterpret_cast<__nv_bfloat162*>(Qlo)[2 * i + 1] = lp1;
    } else {
        const int j = i - nQ4;
        if (j < nK4) {
            const float4 v = reinterpret_cast<const float4*>(Kin)[j];
            __nv_bfloat162 hp0, hp1;
            hp0.x = __float2bfloat16(v.x); hp0.y = __float2bfloat16(v.y);
            hp1.x = __float2bfloat16(v.z); hp1.y = __float2bfloat16(v.w);
            reinterpret_cast<__nv_bfloat162*>(Khi)[2 * j]     = hp0;
            reinterpret_cast<__nv_bfloat162*>(Khi)[2 * j + 1] = hp1;
        }
    }
}

// ---------------------------------------------------------------------------
// Merged weight split + mask probe (one launch).
// ---------------------------------------------------------------------------
__global__ void __launch_bounds__(256)
split_weights_probe_kernel(const float* __restrict__ Wq, const float* __restrict__ Wk,
                           const float* __restrict__ Wv, const float* __restrict__ Wp,
                           const unsigned char* __restrict__ mask,
                           __nv_bfloat16* __restrict__ Wqhi, __nv_bfloat16* __restrict__ Wqlo,
                           __nv_bfloat16* __restrict__ Wkhi, __nv_bfloat16* __restrict__ Wvhi,
                           __nv_bfloat16* __restrict__ Wphi, int nW4) {
    const int i = blockIdx.x * 256 + threadIdx.x;
    const int seg = i / nW4;
    const int j = i - seg * nW4;
    if (seg == 0) {
        const float4 v = reinterpret_cast<const float4*>(Wq)[j];
        __nv_bfloat16 h0 = __float2bfloat16(v.x), h1 = __float2bfloat16(v.y);
        __nv_bfloat16 h2 = __float2bfloat16(v.z), h3 = __float2bfloat16(v.w);
        __nv_bfloat162 hp0; hp0.x = h0; hp0.y = h1;
        __nv_bfloat162 hp1; hp1.x = h2; hp1.y = h3;
        __nv_bfloat162 lp0, lp1;
        lp0.x = __float2bfloat16(v.x - __bfloat162float(h0));
        lp0.y = __float2bfloat16(v.y - __bfloat162float(h1));
        lp1.x = __float2bfloat16(v.z - __bfloat162float(h2));
        lp1.y = __float2bfloat16(v.w - __bfloat162float(h3));
        reinterpret_cast<__nv_bfloat162*>(Wqhi)[2 * j]     = hp0;
        reinterpret_cast<__nv_bfloat162*>(Wqhi)[2 * j + 1] = hp1;
        reinterpret_cast<__nv_bfloat162*>(Wqlo)[2 * j]     = lp0;
        reinterpret_cast<__nv_bfloat162*>(Wqlo)[2 * j + 1] = lp1;
    } else if (seg < 4) {
        const float* W = (seg == 1) ? Wk : (seg == 2) ? Wv : Wp;
        __nv_bfloat16* D = (seg == 1) ? Wkhi : (seg == 2) ? Wvhi : Wphi;
        const float4 v = reinterpret_cast<const float4*>(W)[j];
        __nv_bfloat162 hp0, hp1;
        hp0.x = __float2bfloat16(v.x); hp0.y = __float2bfloat16(v.y);
        hp1.x = __float2bfloat16(v.z); hp1.y = __float2bfloat16(v.w);
        reinterpret_cast<__nv_bfloat162*>(D)[2 * j]     = hp0;
        reinterpret_cast<__nv_bfloat162*>(D)[2 * j + 1] = hp1;
    }
    if (blockIdx.x == 0) {
        __shared__ int found;
        if (threadIdx.x == 0) found = 0;
        __syncthreads();
        for (int t = threadIdx.x; t < 1024; t += 256)
            if (mask[t * 4 + 1] != 0) found = 1;
        __syncthreads();
        if (threadIdx.x == 0) g_mask4 = found ? 0 : 1;
    }
}

// ---------------------------------------------------------------------------
// Mask + softmax, in place on bf16 buffer (coalesced mask read)
// ---------------------------------------------------------------------------
__global__ void __launch_bounds__(256)
softmax_mask_kernel(__nv_bfloat16* __restrict__ p, const void* __restrict__ mask) {
    const long long row = blockIdx.x;
    __nv_bfloat16* pr = p + row * SS;
    const long long mbase = row * SS;
    const int tid = threadIdx.x;
    const int is4 = g_mask4;

    float vals[8];
    float mx = -3.0e38f;
#pragma unroll
    for (int i = 0; i < 8; i += 2) {
        const int c = tid * 2 + (i << 8);           // 2 contiguous per thread
        const __nv_bfloat162 x2 = *reinterpret_cast<const __nv_bfloat162*>(&pr[c]);
        float x0 = __bfloat162float(x2.x);
        float x1 = __bfloat162float(x2.y);
        bool m0, m1;
        if (is4) {
            const uint2 mv = *reinterpret_cast<const uint2*>(
                reinterpret_cast<const unsigned int*>(mask) + mbase + c);
            m0 = mv.x != 0u; m1 = mv.y != 0u;
        } else {
            const unsigned char* mp =
                reinterpret_cast<const unsigned char*>(mask) + mbase + c;
            m0 = mp[0] != 0; m1 = mp[1] != 0;
        }
        x0 = m0 ? -1e9f : x0;
        x1 = m1 ? -1e9f : x1;
        vals[i] = x0; vals[i + 1] = x1;
        mx = fmaxf(mx, fmaxf(x0, x1));
    }
    __shared__ float sred[8];
#pragma unroll
    for (int o = 16; o > 0; o >>= 1) mx = fmaxf(mx, __shfl_xor_sync(0xffffffffu, mx, o));
    if ((tid & 31) == 0) sred[tid >> 5] = mx;
    __syncthreads();
    float bm = sred[0];
#pragma unroll
    for (int w = 1; w < 8; w++) bm = fmaxf(bm, sred[w]);

    float sum = 0.f;
#pragma unroll
    for (int i = 0; i < 8; i++) {
        const float e = __expf(vals[i] - bm);
        vals[i] = e;
        sum += e;
    }
#pragma unroll
    for (int o = 16; o > 0; o >>= 1) sum += __shfl_xor_sync(0xffffffffu, sum, o);
    __shared__ float ssum[8];
    if ((tid & 31) == 0) ssum[tid >> 5] = sum;
    __syncthreads();
    float ts = 0.f;
#pragma unroll
    for (int w = 0; w < 8; w++) ts += ssum[w];

    const float inv = 1.0f / ts;
#pragma unroll
    for (int i = 0; i < 8; i += 2) {
        const int c = tid * 2 + (i << 8);
        __nv_bfloat162 o2;
        o2.x = __float2bfloat16(vals[i] * inv);
        o2.y = __float2bfloat16(vals[i + 1] * inv);
        *reinterpret_cast<__nv_bfloat162*>(&pr[c]) = o2;
    }
}

// ---------------------------------------------------------------------------
// kernel_launch: forked-stream graph (projections in parallel)
// ---------------------------------------------------------------------------
extern "C" void kernel_launch(void* const* d_in, const int* in_sizes, int n_in,
                              void* d_out, int out_size) {
    const float* Q    = (const float*)d_in[0];
    const float* Kin  = (const float*)d_in[1];
    const void*  mask = (const void*)d_in[2];
    const float* Wq   = (const float*)d_in[3];
    const float* Wk   = (const float*)d_in[4];
    const float* Wv   = (const float*)d_in[5];
    const float* Wp   = (const float*)d_in[6];
    const float* bp   = (const float*)d_in[7];
    float* out        = (float*)d_out;

    __nv_bfloat16 *Qhi, *Qlo, *Khi, *Wqhi, *Wqlo, *Wkhi, *Wvhi, *Wphi2;
    __nv_bfloat16 *qhi, *khi, *vThi, *phi, *aohi;
    float *qf;
    cudaGetSymbolAddress((void**)&Qhi, g_Qhi);   cudaGetSymbolAddress((void**)&Qlo, g_Qlo);
    cudaGetSymbolAddress((void**)&Khi, g_Khi);
    cudaGetSymbolAddress((void**)&Wqhi, g_Wqhi); cudaGetSymbolAddress((void**)&Wqlo, g_Wqlo);
    cudaGetSymbolAddress((void**)&Wkhi, g_Wkhi);
    cudaGetSymbolAddress((void**)&Wvhi, g_Wvhi);
    cudaGetSymbolAddress((void**)&Wphi2, g_Wphi);
    cudaGetSymbolAddress((void**)&qf, g_qf);
    cudaGetSymbolAddress((void**)&qhi, g_qhi);
    cudaGetSymbolAddress((void**)&khi, g_khi);
    cudaGetSymbolAddress((void**)&vThi, g_vThi);
    cudaGetSymbolAddress((void**)&phi, g_phi);
    cudaGetSymbolAddress((void**)&aohi, g_aohi);

    constexpr int SM_1 = 3 * ((128 + 128) * PITCH);          // 110592/CTA, 2 CTA/SM
    constexpr int SM_3 = 3 * ((2 * 128 + 2 * 128) * PITCH);  // 221184, 1 CTA/SM
    cudaFuncSetAttribute(hmma_gemm<128, 3, 3, 1, false, false, true,  true >,
                         cudaFuncAttributeMaxDynamicSharedMemorySize, SM_3);
    cudaFuncSetAttribute(hmma_gemm<128, 3, 1, 2, false, false, false, true >,
                         cudaFuncAttributeMaxDynamicSharedMemorySize, SM_1);
    cudaFuncSetAttribute(hmma_gemm<128, 3, 1, 2, true,  true,  true,  false>,
                         cudaFuncAttributeMaxDynamicSharedMemorySize, SM_1);

    // Static side streams/events (created on the first, non-captured call;
    // reused as graph forks during capture).
    static cudaStream_t s1 = nullptr, s2 = nullptr;
    static cudaEvent_t  e0 = nullptr, ek = nullptr, ev = nullptr;
    if (!s1) {
        cudaStreamCreateWithFlags(&s1, cudaStreamNonBlocking);
        cudaStreamCreateWithFlags(&s2, cudaStreamNonBlocking);
        cudaEventCreateWithFlags(&e0, cudaEventDisableTiming);
        cudaEventCreateWithFlags(&ek, cudaEventDisableTiming);
        cudaEventCreateWithFlags(&ev, cudaEventDisableTiming);
    }

    const float scale = 0.04419417382415922f;  // 512^-0.5
    const long long sQKV = (long long)SS * EE;
    const long long sSC  = (long long)SS * SS;
    dim3 blk(256);
    const int nQ4 = MTOT * EE / 4, nW4 = EE * EE / 4;

    // Prep (2 launches, main stream)
    split_inputs_kernel<<<(2 * nQ4 + 255) / 256, blk>>>(Q, Kin, Qhi, Qlo, Khi, nQ4, nQ4);
    split_weights_probe_kernel<<<(4 * nW4 + 255) / 256, blk>>>(
        Wq, Wk, Wv, Wp, (const unsigned char*)mask,
        Wqhi, Wqlo, Wkhi, Wvhi, Wphi2, nW4);

    // Fork: projections run in parallel
    cudaEventRecord(e0, 0);
    cudaStreamWaitEvent(s1, e0, 0);
    cudaStreamWaitEvent(s2, e0, 0);

    // main: q = Q Wq^T (3-product; residual-critical) -> qf fp32 + qhi
    hmma_gemm<128, 3, 3, 1, false, false, true, true>
        <<<dim3(EE / 128, MTOT / 128, 1), blk, SM_3>>>(
        Qhi, Qlo, Wqhi, Wqlo, qf, qhi, MTOT, EE, EE, 0, 0, 0, 1.f, nullptr, nullptr);
    // s1: k = K Wk^T (1-product) -> khi
    hmma_gemm<128, 3, 1, 2, false, false, false, true>
        <<<dim3(EE / 128, MTOT / 128, 1), blk, SM_1, s1>>>(
        Khi, nullptr, Wkhi, nullptr, nullptr, khi, MTOT, EE, EE,
        0, 0, 0, 1.f, nullptr, nullptr);
    cudaEventRecord(ek, s1);
    // s2: vT[b] = Wv K[b]^T (1-product) -> vThi
    hmma_gemm<128, 3, 1, 2, false, false, false, true>
        <<<dim3(SS / 128, EE / 128, BB), blk, SM_1, s2>>>(
        Wvhi, nullptr, Khi, nullptr, nullptr, vThi, EE, SS, EE,
        0, sQKV, (long long)EE * SS, 1.f, nullptr, nullptr);
    cudaEventRecord(ev, s2);

    // main waits for k; scores overlap with v-proj tail
    cudaStreamWaitEvent(0, ek, 0);
    // scores[b] = scale * q[b] k[b]^T (1-product) -> bf16 into phi
    hmma_gemm<128, 3, 1, 2, false, false, false, true>
        <<<dim3(SS / 128, SS / 128, BB), blk, SM_1>>>(
        qhi, nullptr, khi, nullptr, nullptr, phi, SS, SS, EE,
        sQKV, sQKV, sSC, scale, nullptr, nullptr);
    // mask + softmax in place on phi
    softmax_mask_kernel<<<BB * SS, blk>>>(phi, mask);

    // main waits for v before attn·v
    cudaStreamWaitEvent(0, ev, 0);
    // ao[b] = p[b] vT[b]^T (1-product) -> aohi
    hmma_gemm<128, 3, 1, 2, false, false, false, true>
        <<<dim3(EE / 128, SS / 128, BB), blk, SM_1>>>(
        phi, nullptr, vThi, nullptr, nullptr, aohi, SS, EE, SS,
        sSC, (long long)EE * SS, sQKV, 1.f, nullptr, nullptr);
    // out = ao Wp^T + bp + q (1-product + bias + residual)
    hmma_gemm<128, 3, 1, 2, true, true, true, false>
        <<<dim3(EE / 128, MTOT / 128, 1), blk, SM_1>>>(
        aohi, nullptr, Wphi2, nullptr, out, nullptr, MTOT, EE, EE,
        0, 0, 0, 1.f, bp, qf);
}